// round 6
// baseline (speedup 1.0000x reference)
#include <cuda_runtime.h>
#include <cuda_fp16.h>
#include <math.h>
#include <stdint.h>

// HashEmbedder: 16-level 2D multires hash grid, 2 feats/level, T=2^19.
// Phase 1: build fp16 cell-packed corner table (16B per cell).
// Phase 2: 8 levels per thread -> 8 independent LDG.128 gathers (MLP=8),
// 4 coalesced float4 stores per thread (64B; 2 threads = one 128B line).

#define NLEV 16
#define TLOG2 19
#define TSIZE (1u << TLOG2)
#define HMASK ((1u << TLOG2) - 1u)
#define PRIME1 2654435761u

// Sum of res^2 over the 16 levels = 706,816 cells; margin for safety.
#define MAX_CELLS 710000
__device__ uint4 g_packed[MAX_CELLS];   // 16B per cell: h00,h10,h01,h11

struct Params {
    float resF[NLEV];
    int   resI[NLEV];
    int   off[NLEV + 1];
};

// ---------------------------------------------------------------------------
// Phase 1: build packed table. One thread per cell.
// ---------------------------------------------------------------------------
__global__ __launch_bounds__(256) void build_packed_kernel(
    const float* __restrict__ emb, Params pm, int total_cells)
{
    int i = blockIdx.x * blockDim.x + threadIdx.x;
    if (i >= total_cells) return;

    int l = 0;
#pragma unroll
    for (int k = 1; k < NLEV; ++k) l += (i >= pm.off[k]);

    int c   = i - pm.off[l];
    int res = pm.resI[l];
    int cy  = c / res;
    int cx  = c - cy * res;

    uint32_t ux0 = (uint32_t)cx;
    uint32_t ux1 = (uint32_t)(cx + 1);
    uint32_t yp0 = (uint32_t)cy * PRIME1;
    uint32_t yp1 = (uint32_t)(cy + 1) * PRIME1;

    uint32_t a00 = (ux0 ^ yp0) & HMASK;
    uint32_t a10 = (ux1 ^ yp0) & HMASK;
    uint32_t a01 = (ux0 ^ yp1) & HMASK;
    uint32_t a11 = (ux1 ^ yp1) & HMASK;

    const float2* __restrict__ tab =
        ((const float2*)emb) + ((size_t)l << TLOG2);

    float2 f00 = __ldg(tab + a00);
    float2 f10 = __ldg(tab + a10);
    float2 f01 = __ldg(tab + a01);
    float2 f11 = __ldg(tab + a11);

    half2 h00 = __float22half2_rn(f00);
    half2 h10 = __float22half2_rn(f10);
    half2 h01 = __float22half2_rn(f01);
    half2 h11 = __float22half2_rn(f11);

    uint4 r;
    r.x = *(const uint32_t*)&h00;
    r.y = *(const uint32_t*)&h10;
    r.z = *(const uint32_t*)&h01;
    r.w = *(const uint32_t*)&h11;
    g_packed[i] = r;
}

// ---------------------------------------------------------------------------
// Phase 2: one thread per (point, 8-level group). MLP=8 gathers.
// ---------------------------------------------------------------------------
__global__ __launch_bounds__(256, 4) void hash_embed_kernel(
    const float* __restrict__ x,
    float* __restrict__ out,
    int n_points,
    Params pm)
{
    __shared__ float s_resF[NLEV];
    __shared__ int   s_resI[NLEV];
    __shared__ int   s_off[NLEV];
    if (threadIdx.x < NLEV) {
        s_resF[threadIdx.x] = pm.resF[threadIdx.x];
        s_resI[threadIdx.x] = pm.resI[threadIdx.x];
        s_off[threadIdx.x]  = pm.off[threadIdx.x];
    }
    __syncthreads();

    int gid = blockIdx.x * blockDim.x + threadIdx.x;
    int p = gid >> 1;              // point index (2 threads per point)
    if (p >= n_points) return;
    int lb = (gid & 1) << 3;       // base level: 0 or 8

    // 2 consecutive threads read the same point -> broadcast load
    float2 xy = __ldg(((const float2*)x) + p);

    // Compute 8 cell indices (keep only idx live across the load burst;
    // wx/wy are rematerialized cheaply after loads).
    int idx[8];
#pragma unroll
    for (int j = 0; j < 8; ++j) {
        int   l   = lb + j;
        float res = s_resF[l];
        int   ri  = s_resI[l];
        int   off = s_off[l];

        int ix = min(max((int)floorf(xy.x * res), 0), ri - 1);
        int iy = min(max((int)floorf(xy.y * res), 0), ri - 1);
        idx[j] = off + iy * ri + ix;
    }

    // 8 independent gathers, issued back-to-back
    uint4 rr[8];
#pragma unroll
    for (int j = 0; j < 8; ++j) rr[j] = __ldg(&g_packed[idx[j]]);

    float4 o[4];
#pragma unroll
    for (int j = 0; j < 8; ++j) {
        int   l   = lb + j;
        float res = s_resF[l];
        float px = xy.x * res;
        float py = xy.y * res;
        float wx = px - floorf(px);
        float wy = py - floorf(py);

        float2 f00 = __half22float2(*(const half2*)&rr[j].x);
        float2 f10 = __half22float2(*(const half2*)&rr[j].y);
        float2 f01 = __half22float2(*(const half2*)&rr[j].z);
        float2 f11 = __half22float2(*(const half2*)&rr[j].w);

        float u = 1.0f - wx;
        float v = 1.0f - wy;

        float ox = (f00.x * u + f10.x * wx) * v + (f01.x * u + f11.x * wx) * wy;
        float oy = (f00.y * u + f10.y * wx) * v + (f01.y * u + f11.y * wx) * wy;

        ((float*)o)[2 * j]     = ox;
        ((float*)o)[2 * j + 1] = oy;
    }

    // out row = p*32 floats; this thread covers floats [lb*2, lb*2+16) = 64B.
    // 2 threads per point -> a full 128B line, perfectly coalesced.
    float4* dst = (float4*)(out + (size_t)p * (NLEV * 2) + lb * 2);
    dst[0] = o[0];
    dst[1] = o[1];
    dst[2] = o[2];
    dst[3] = o[3];
}

extern "C" void kernel_launch(void* const* d_in, const int* in_sizes, int n_in,
                              void* d_out, int out_size)
{
    const float* x   = (const float*)d_in[0];
    const float* emb = (const float*)d_in[1];
    float* out       = (float*)d_out;

    int n_points = in_sizes[0] / 2;

    Params pm;
    double b = exp((log(512.0) - log(16.0)) / 15.0);
    int acc = 0;
    for (int l = 0; l < NLEV; ++l) {
        double r = floor(16.0 * pow(b, (double)l));
        pm.resF[l] = (float)r;
        pm.resI[l] = (int)r;
        pm.off[l]  = acc;
        acc += pm.resI[l] * pm.resI[l];
    }
    pm.off[NLEV] = acc;

    // Phase 1: build packed corner table (fp16, 16B per cell)
    {
        int threads = 256;
        int blocks = (acc + threads - 1) / threads;
        build_packed_kernel<<<blocks, threads>>>(emb, pm, acc);
    }

    // Phase 2: gather + lerp, 2 threads per point
    {
        long long total = (long long)n_points * 2;
        int threads = 256;
        int blocks = (int)((total + threads - 1) / threads);
        hash_embed_kernel<<<blocks, threads>>>(x, out, n_points, pm);
    }
}